// round 15
// baseline (speedup 1.0000x reference)
#include <cuda_runtime.h>
#include <cuda_fp16.h>
#include <cstdint>

#define NDIM    128
#define EDIM    64
#define KDIM    192
#define BM      192                       // edges per CTA tile (6 warp-rows x 32)
#define THREADS 384
#define NKK     12                        // K steps of 16 (fp16 mma)

#define AS_WROW 100                       // A row stride in 32-bit words (400B)
#define AS_BUF_BYTES (BM * AS_WROW * 4)   // 76800 B per buffer
#define WF_WORDS (2 * NKK * 32 * 20)      // 15360 words (16 used + 4 pad)

#define OFF_MBAR 0                        // two mbarriers @0, @8
#define OFF_BIAS 16                       // 128 f32
#define OFF_WF   1024
#define OFF_AS   (OFF_WF + WF_WORDS * 4)  // 62464
#define SMEM_TOTAL (OFF_AS + 2 * AS_BUF_BYTES)   // 216064 B -> 1 CTA/SM

#define ATOM_CAP_ROWS 16384
__device__ __half g_atom_h[ATOM_CAP_ROWS * NDIM];
__device__ int    g_idx_is64;

// merged prep: block 0 detects index dtype; all blocks convert atom table to fp16
__global__ void prep_kernel(const float* __restrict__ a, long n,
                            const int* __restrict__ idxbuf, int n_words, int do_cvt) {
    if (blockIdx.x == 0) {
        __shared__ int nz;
        if (threadIdx.x == 0) nz = 0;
        __syncthreads();
        int local = 0;
        for (int i = 1 + 2 * threadIdx.x; i < n_words; i += 2 * blockDim.x)
            local += (idxbuf[i] != 0);
        if (local) atomicAdd(&nz, 1);
        __syncthreads();
        if (threadIdx.x == 0) g_idx_is64 = (nz == 0) ? 1 : 0;
    }
    if (do_cvt) {
        for (long i = blockIdx.x * (long)blockDim.x + threadIdx.x; i < n;
             i += (long)gridDim.x * blockDim.x)
            g_atom_h[i] = __float2half_rn(a[i]);
    }
}

__device__ __forceinline__ void mma_f16(float d[4], const uint32_t a[4], const uint32_t b[2]) {
    asm volatile(
        "mma.sync.aligned.m16n8k16.row.col.f32.f16.f16.f32 "
        "{%0,%1,%2,%3}, {%4,%5,%6,%7}, {%8,%9}, {%0,%1,%2,%3};\n"
        : "+f"(d[0]), "+f"(d[1]), "+f"(d[2]), "+f"(d[3])
        : "r"(a[0]), "r"(a[1]), "r"(a[2]), "r"(a[3]),
          "r"(b[0]), "r"(b[1]));
}
__device__ __forceinline__ void ldsm_x4(uint32_t a[4], uint32_t addr) {
    asm volatile("ldmatrix.sync.aligned.m8n8.x4.shared.b16 {%0,%1,%2,%3}, [%4];"
        : "=r"(a[0]), "=r"(a[1]), "=r"(a[2]), "=r"(a[3]) : "r"(addr));
}
__device__ __forceinline__ uint32_t smem_u32(const void* p) {
    uint32_t a;
    asm("{ .reg .u64 t; cvta.to.shared.u64 t, %1; cvt.u32.u64 %0, t; }" : "=r"(a) : "l"(p));
    return a;
}
__device__ __forceinline__ uint32_t pack_h2(float x, float y) {
    __half2 h = __floats2half2_rn(x, y);
    return *(uint32_t*)&h;
}

#define MBAR_INIT(mb, c) \
    asm volatile("mbarrier.init.shared.b64 [%0], %1;" :: "r"(mb), "r"((uint32_t)(c)) : "memory")
#define MBAR_ARRIVE(mb) \
    asm volatile("mbarrier.arrive.shared::cta.b64 _, [%0];" :: "r"(mb) : "memory")
#define MBAR_ARRIVE_TX(mb, tx) \
    asm volatile("mbarrier.arrive.expect_tx.shared::cta.b64 _, [%0], %1;" \
                 :: "r"(mb), "r"((uint32_t)(tx)) : "memory")
#define MBAR_WAIT(mb, ph) do { \
    asm volatile("{\n\t.reg .pred P1;\n\t" \
        "WL_%=:\n\t" \
        "mbarrier.try_wait.parity.acquire.cta.shared::cta.b64 P1, [%0], %1, 0x989680;\n\t" \
        "@P1 bra.uni WD_%=;\n\t" \
        "bra.uni WL_%=;\n\t" \
        "WD_%=:\n\t}" :: "r"(mb), "r"((uint32_t)(ph)) : "memory"); \
} while (0)
#define BULK_CP(dst, src, bytes, mb) \
    asm volatile("cp.async.bulk.shared::cta.global.mbarrier::complete_tx::bytes [%0], [%1], %2, [%3];" \
                 :: "r"(dst), "l"(src), "r"((uint32_t)(bytes)), "r"(mb) : "memory")

// ---- edge staging: LDG into regs early, STS later ----
__device__ __forceinline__ void edge_ldg(float4 ev[8], long tile,
                                         const float* __restrict__ edge, int E) {
    const int tid = threadIdx.x;
    const long eb = tile * (long)BM;
    const long vr = (long)E - eb;
    const int vf4 = (int)((vr * (EDIM / 4) < (long)BM * 16) ? vr * (EDIM / 4) : (long)BM * 16);
    const float4* base = (const float4*)(edge + eb * EDIM);
    #pragma unroll
    for (int u = 0; u < 8; u++) {
        const int f4 = u * THREADS + tid;
        ev[u] = (f4 < vf4) ? __ldg(base + f4) : make_float4(0.f, 0.f, 0.f, 0.f);
    }
}
__device__ __forceinline__ void edge_sts(const float4 ev[8], uint32_t* __restrict__ As32,
                                         long tile, int E) {
    const int tid = threadIdx.x;
    const long vr = (long)E - tile * (long)BM;
    const int vf4 = (int)((vr * (EDIM / 4) < (long)BM * 16) ? vr * (EDIM / 4) : (long)BM * 16);
    #pragma unroll
    for (int u = 0; u < 8; u++) {
        const int f4 = u * THREADS + tid;
        if (f4 < vf4) {
            const int r = f4 >> 4;
            uint32_t* dst = As32 + r * AS_WROW + 64 + (f4 & 15) * 2;
            dst[0] = pack_h2(ev[u].x, ev[u].y);
            dst[1] = pack_h2(ev[u].z, ev[u].w);
        }
    }
}

__device__ __forceinline__ long idx_ld(long tile, const void* __restrict__ src_idx,
                                       int is64, int E, long n_nodes) {
    const int tid = threadIdx.x;
    long s = 0;
    if (tid < BM) {
        const long e = tile * (long)BM + tid;
        if (e < (long)E) {
            s = is64 ? (long)((const long long*)src_idx)[e]
                     : (long)((const int*)src_idx)[e];
            if (s < 0) s = 0;
            if (s >= n_nodes) s = n_nodes - 1;
        }
    }
    return s;
}
__device__ __forceinline__ void atom_issue(uint32_t as_smem, uint32_t mbar, long tile,
                                           long s, int E) {
    const int tid = threadIdx.x;
    if (tid < BM && (tile * (long)BM + tid) < (long)E) {
        MBAR_ARRIVE_TX(mbar, NDIM * 2);
        BULK_CP(as_smem + (uint32_t)(tid * AS_WROW * 4),
                (const void*)(g_atom_h + s * (long)NDIM), NDIM * 2, mbar);
    } else {
        MBAR_ARRIVE(mbar);
    }
}
// fallback (n_nodes > cap): 2 threads/row
__device__ __forceinline__ void atom_fallback(uint32_t* __restrict__ As32, long tile,
                                              const float* __restrict__ atom,
                                              const void* __restrict__ src_idx,
                                              int is64, int E, long n_nodes) {
    const int tid  = threadIdx.x;
    const int r    = tid >> 1;
    const int half = tid & 1;
    const long e   = tile * (long)BM + r;
    if (e >= (long)E) return;
    long s = is64 ? (long)((const long long*)src_idx)[e]
                  : (long)((const int*)src_idx)[e];
    if (s < 0) s = 0;
    if (s >= n_nodes) s = n_nodes - 1;
    const float4* arow = (const float4*)(atom + s * (long)NDIM) + half * 16;
    uint32_t* dst = As32 + r * AS_WROW + half * 32;
    #pragma unroll
    for (int u = 0; u < 16; u++) {
        float4 v = __ldg(arow + u);
        dst[u * 2 + 0] = pack_h2(v.x, v.y);
        dst[u * 2 + 1] = pack_h2(v.z, v.w);
    }
}

__device__ __forceinline__ void load_b16(uint32_t b[16], const uint32_t* __restrict__ Wr) {
    uint4 q0 = *(const uint4*)(Wr + 0);
    uint4 q1 = *(const uint4*)(Wr + 4);
    uint4 q2 = *(const uint4*)(Wr + 8);
    uint4 q3 = *(const uint4*)(Wr + 12);
    b[0]=q0.x;  b[1]=q0.y;  b[2]=q0.z;  b[3]=q0.w;
    b[4]=q1.x;  b[5]=q1.y;  b[6]=q1.z;  b[7]=q1.w;
    b[8]=q2.x;  b[9]=q2.y;  b[10]=q2.z; b[11]=q2.w;
    b[12]=q3.x; b[13]=q3.y; b[14]=q3.z; b[15]=q3.w;
}

__global__ void __launch_bounds__(THREADS, 1)
atom2bond_kernel(const float* __restrict__ atom,
                 const float* __restrict__ edge,
                 const void*  __restrict__ src_idx,
                 const float* __restrict__ Wg,
                 const float* __restrict__ bg,
                 float* __restrict__ out,
                 int E, int ntiles, long n_nodes, int fast) {
    extern __shared__ char sm[];
    const uint32_t smb = smem_u32(sm);
    uint32_t* Wf = (uint32_t*)(sm + OFF_WF);
    float* Bs = (float*)(sm + OFF_BIAS);

    const int tid  = threadIdx.x;
    const int lane = tid & 31;
    const int warp = tid >> 5;            // 0..11
    const int g  = lane >> 2;
    const int t  = lane & 3;
    const int wm = warp >> 1;             // 0..5 : 32-edge block
    const int wn = warp & 1;              // 0..1 : 64-col half
    const int is64 = g_idx_is64;

    if (tid == 0) { MBAR_INIT(smb + OFF_MBAR, THREADS); MBAR_INIT(smb + OFF_MBAR + 8, THREADS); }
    __syncthreads();

    // ---- prologue: tile 0 into buffer 0 ----
    long tile = blockIdx.x;
    uint32_t* As0 = (uint32_t*)(sm + OFF_AS);
    if (fast) {
        long s0 = idx_ld(tile, src_idx, is64, E, n_nodes);
        atom_issue(smb + OFF_AS, smb + OFF_MBAR, tile, s0, E);
    } else {
        atom_fallback(As0, tile, atom, src_idx, is64, E, n_nodes);
        MBAR_ARRIVE(smb + OFF_MBAR);
    }
    float4 ev[8];
    edge_ldg(ev, tile, edge, E);
    edge_sts(ev, As0, tile, E);

    // ---- W fragments in smem (per-lane contiguous, stride 20 words) + bias ----
    for (int idx = tid; idx < 2 * NKK * 32 * 16; idx += THREADS) {
        const int v  = idx & 15;
        const int l  = (idx >> 4) & 31;
        const int rk = idx >> 9;
        const int kk = rk % NKK;
        const int wq = rk / NKK;
        const int j  = v >> 1;
        const int h  = v & 1;
        const int k  = kk * 16 + h * 8 + 2 * (l & 3);
        const int n  = wq * 64 + j * 8 + (l >> 2);
        Wf[((wq * NKK + kk) * 32 + l) * 20 + v] =
            pack_h2(Wg[k * NDIM + n], Wg[(k + 1) * NDIM + n]);
    }
    if (tid < NDIM) Bs[tid] = bg[tid];
    __syncthreads();

    const uint32_t* Wbase = Wf + (wn * NKK * 32 + lane) * 20;
    // per-lane ldmatrix base offset (bytes): row = wm*32 + (lane&15), chunk = lane>>4
    const uint32_t a_off = (uint32_t)((wm * 32 + (lane & 15)) * AS_WROW * 4 + (lane >> 4) * 16);

    uint32_t ph[2] = {0, 0};
    int bi = 0;
    for (;;) {
        const long tn = tile + gridDim.x;
        const bool more = (tn < (long)ntiles);
        const int  bn = bi ^ 1;
        uint32_t* Asnxt = (uint32_t*)(sm + OFF_AS + bn * AS_BUF_BYTES);

        // issue next tile's staging BEFORE waiting on this tile's atoms —
        // buf[bn] readers all crossed the previous barrier, so this is safe
        // and gets bulk-copies + edge LDGs in flight as early as possible.
        if (more) {
            if (fast) {
                long sn = idx_ld(tn, src_idx, is64, E, n_nodes);
                atom_issue(smb + OFF_AS + bn * AS_BUF_BYTES, smb + OFF_MBAR + bn * 8, tn, sn, E);
            }
            edge_ldg(ev, tn, edge, E);
        }

        MBAR_WAIT(smb + OFF_MBAR + bi * 8, ph[bi]);    // atoms(tile) landed in buf[bi]
        ph[bi] ^= 1;

        // ---- MMA: warp = 32 edges x 64 outputs, K=192; b double-buffered ----
        float acc[2][8][4];
        #pragma unroll
        for (int i = 0; i < 2; i++)
            #pragma unroll
            for (int j = 0; j < 8; j++)
                #pragma unroll
                for (int c = 0; c < 4; c++) acc[i][j][c] = 0.f;

        const uint32_t a_base = smb + OFF_AS + (uint32_t)(bi * AS_BUF_BYTES) + a_off;

        uint32_t b[2][16];
        load_b16(b[0], Wbase);
        #pragma unroll
        for (int kk = 0; kk < NKK; kk++) {
            const int cur = kk & 1;
            if (kk < NKK - 1)
                load_b16(b[cur ^ 1], Wbase + (kk + 1) * 640);
            uint32_t a[2][4];
            ldsm_x4(a[0], a_base + kk * 32);
            ldsm_x4(a[1], a_base + 16 * AS_WROW * 4 + kk * 32);
            #pragma unroll
            for (int i = 0; i < 2; i++)
                #pragma unroll
                for (int j = 0; j < 8; j++)
                    mma_f16(acc[i][j], a[i], b[cur] + 2 * j);
        }

        // ---- stage next tile's edges into buf[bn], then barrier BEFORE the
        // epilogue: warp-skew in the STG tail no longer serializes the CTA ----
        if (more) {
            edge_sts(ev, Asnxt, tn, E);
            if (!fast) {
                atom_fallback(Asnxt, tn, atom, src_idx, is64, E, n_nodes);
                MBAR_ARRIVE(smb + OFF_MBAR + bn * 8);
            }
            __syncthreads();   // buf[bi] fully read by all warps; buf[bn] staging visible
        }

        // ---- epilogue(tile): bias + relu + STG from regs (overlaps other
        // warps already waiting on / starting tile t+1) ----
        const long eb = tile * (long)BM;
        #pragma unroll
        for (int i = 0; i < 2; i++) {
            #pragma unroll
            for (int rr = 0; rr < 2; rr++) {
                const long e = eb + wm * 32 + i * 16 + rr * 8 + g;
                if (e < (long)E) {
                    float* orow = out + e * (long)NDIM;
                    #pragma unroll
                    for (int j = 0; j < 8; j++) {
                        const int c = wn * 64 + j * 8 + 2 * t;
                        const float2 bc = *(const float2*)(Bs + c);
                        float v0 = fmaxf(acc[i][j][rr * 2 + 0] + bc.x, 0.f);
                        float v1 = fmaxf(acc[i][j][rr * 2 + 1] + bc.y, 0.f);
                        *(float2*)(orow + c) = make_float2(v0, v1);
                    }
                }
            }
        }

        if (!more) break;
        tile = tn;
        bi = bn;
    }
}

extern "C" void kernel_launch(void* const* d_in, const int* in_sizes, int n_in,
                              void* d_out, int out_size) {
    const float* atom = (const float*)d_in[0];   // [N_NODES,128] f32
    const float* edge = (const float*)d_in[1];   // [E,64] f32
    const void*  src  = d_in[2];                 // [E] int32 or int64 (detected)
    const float* W    = (const float*)d_in[3];   // [192,128] f32
    const float* b    = (const float*)d_in[4];   // [128] f32
    float* out = (float*)d_out;                  // [E,128] f32

    const int  E       = in_sizes[2];
    const long n_atomf = (long)in_sizes[0];
    const long n_nodes = n_atomf / NDIM;
    const int  ntiles  = (E + BM - 1) / BM;
    const int  fast    = (n_nodes <= ATOM_CAP_ROWS) ? 1 : 0;

    int n_words = E < 1024 ? E : 1024;
    prep_kernel<<<148, 256>>>(atom, n_atomf, (const int*)src, n_words, fast);

    cudaFuncSetAttribute(atom2bond_kernel,
                         cudaFuncAttributeMaxDynamicSharedMemorySize, SMEM_TOTAL);

    int grid = ntiles < 148 ? ntiles : 148;
    atom2bond_kernel<<<grid, THREADS, SMEM_TOTAL>>>(atom, edge, src, W, b, out,
                                                    E, ntiles, n_nodes, fast);
}

// round 16
// speedup vs baseline: 1.1821x; 1.1821x over previous
#include <cuda_runtime.h>
#include <cuda_fp16.h>
#include <cstdint>

#define NDIM    128
#define EDIM    64
#define KDIM    192
#define BM      192                       // edges per CTA tile (6 warp-rows x 32)
#define THREADS 384
#define NKK     12                        // K steps of 16 (fp16 mma)

#define AS_WROW 100                       // A row stride in 32-bit words (400B)
#define AS_BUF_BYTES (BM * AS_WROW * 4)   // 76800 B per buffer
#define WF_WORDS (2 * NKK * 32 * 20)      // 15360 words (16 used + 4 pad)

#define OFF_MBAR 0                        // two mbarriers @0, @8
#define OFF_BIAS 16                       // 128 f32
#define OFF_WF   1024
#define OFF_AS   (OFF_WF + WF_WORDS * 4)  // 62464
#define SMEM_TOTAL (OFF_AS + 2 * AS_BUF_BYTES)   // 216064 B -> 1 CTA/SM

#define ATOM_CAP_ROWS 16384
__device__ __half g_atom_h[ATOM_CAP_ROWS * NDIM];
__device__ int    g_idx_is64;

// merged prep: block 0 detects index dtype; all blocks convert atom table to fp16
__global__ void prep_kernel(const float* __restrict__ a, long n,
                            const int* __restrict__ idxbuf, int n_words, int do_cvt) {
    if (blockIdx.x == 0) {
        __shared__ int nz;
        if (threadIdx.x == 0) nz = 0;
        __syncthreads();
        int local = 0;
        for (int i = 1 + 2 * threadIdx.x; i < n_words; i += 2 * blockDim.x)
            local += (idxbuf[i] != 0);
        if (local) atomicAdd(&nz, 1);
        __syncthreads();
        if (threadIdx.x == 0) g_idx_is64 = (nz == 0) ? 1 : 0;
    }
    if (do_cvt) {
        for (long i = blockIdx.x * (long)blockDim.x + threadIdx.x; i < n;
             i += (long)gridDim.x * blockDim.x)
            g_atom_h[i] = __float2half_rn(a[i]);
    }
}

__device__ __forceinline__ void mma_f16(float d[4], const uint32_t a[4], const uint32_t b[2]) {
    asm volatile(
        "mma.sync.aligned.m16n8k16.row.col.f32.f16.f16.f32 "
        "{%0,%1,%2,%3}, {%4,%5,%6,%7}, {%8,%9}, {%0,%1,%2,%3};\n"
        : "+f"(d[0]), "+f"(d[1]), "+f"(d[2]), "+f"(d[3])
        : "r"(a[0]), "r"(a[1]), "r"(a[2]), "r"(a[3]),
          "r"(b[0]), "r"(b[1]));
}
__device__ __forceinline__ void ldsm_x4(uint32_t a[4], uint32_t addr) {
    asm volatile("ldmatrix.sync.aligned.m8n8.x4.shared.b16 {%0,%1,%2,%3}, [%4];"
        : "=r"(a[0]), "=r"(a[1]), "=r"(a[2]), "=r"(a[3]) : "r"(addr));
}
__device__ __forceinline__ uint32_t smem_u32(const void* p) {
    uint32_t a;
    asm("{ .reg .u64 t; cvta.to.shared.u64 t, %1; cvt.u32.u64 %0, t; }" : "=r"(a) : "l"(p));
    return a;
}
__device__ __forceinline__ uint32_t pack_h2(float x, float y) {
    __half2 h = __floats2half2_rn(x, y);
    return *(uint32_t*)&h;
}

#define MBAR_INIT(mb, c) \
    asm volatile("mbarrier.init.shared.b64 [%0], %1;" :: "r"(mb), "r"((uint32_t)(c)) : "memory")
#define MBAR_ARRIVE(mb) \
    asm volatile("mbarrier.arrive.shared::cta.b64 _, [%0];" :: "r"(mb) : "memory")
#define MBAR_ARRIVE_TX(mb, tx) \
    asm volatile("mbarrier.arrive.expect_tx.shared::cta.b64 _, [%0], %1;" \
                 :: "r"(mb), "r"((uint32_t)(tx)) : "memory")
#define MBAR_WAIT(mb, ph) do { \
    asm volatile("{\n\t.reg .pred P1;\n\t" \
        "WL_%=:\n\t" \
        "mbarrier.try_wait.parity.acquire.cta.shared::cta.b64 P1, [%0], %1, 0x989680;\n\t" \
        "@P1 bra.uni WD_%=;\n\t" \
        "bra.uni WL_%=;\n\t" \
        "WD_%=:\n\t}" :: "r"(mb), "r"((uint32_t)(ph)) : "memory"); \
} while (0)
#define BULK_CP(dst, src, bytes, mb) \
    asm volatile("cp.async.bulk.shared::cta.global.mbarrier::complete_tx::bytes [%0], [%1], %2, [%3];" \
                 :: "r"(dst), "l"(src), "r"((uint32_t)(bytes)), "r"(mb) : "memory")

// ---- edge staging: LDG into regs early, STS later ----
__device__ __forceinline__ void edge_ldg(float4 ev[8], long tile,
                                         const float* __restrict__ edge, int E) {
    const int tid = threadIdx.x;
    const long eb = tile * (long)BM;
    const long vr = (long)E - eb;
    const int vf4 = (int)((vr * (EDIM / 4) < (long)BM * 16) ? vr * (EDIM / 4) : (long)BM * 16);
    const float4* base = (const float4*)(edge + eb * EDIM);
    #pragma unroll
    for (int u = 0; u < 8; u++) {
        const int f4 = u * THREADS + tid;
        ev[u] = (f4 < vf4) ? __ldg(base + f4) : make_float4(0.f, 0.f, 0.f, 0.f);
    }
}
__device__ __forceinline__ void edge_sts(const float4 ev[8], uint32_t* __restrict__ As32,
                                         long tile, int E) {
    const int tid = threadIdx.x;
    const long vr = (long)E - tile * (long)BM;
    const int vf4 = (int)((vr * (EDIM / 4) < (long)BM * 16) ? vr * (EDIM / 4) : (long)BM * 16);
    #pragma unroll
    for (int u = 0; u < 8; u++) {
        const int f4 = u * THREADS + tid;
        if (f4 < vf4) {
            const int r = f4 >> 4;
            uint32_t* dst = As32 + r * AS_WROW + 64 + (f4 & 15) * 2;
            dst[0] = pack_h2(ev[u].x, ev[u].y);
            dst[1] = pack_h2(ev[u].z, ev[u].w);
        }
    }
}

__device__ __forceinline__ long idx_ld(long tile, const void* __restrict__ src_idx,
                                       int is64, int E, long n_nodes) {
    const int tid = threadIdx.x;
    long s = 0;
    if (tid < BM) {
        const long e = tile * (long)BM + tid;
        if (e < (long)E) {
            s = is64 ? (long)((const long long*)src_idx)[e]
                     : (long)((const int*)src_idx)[e];
            if (s < 0) s = 0;
            if (s >= n_nodes) s = n_nodes - 1;
        }
    }
    return s;
}
__device__ __forceinline__ void atom_issue(uint32_t as_smem, uint32_t mbar, long tile,
                                           long s, int E) {
    const int tid = threadIdx.x;
    if (tid < BM && (tile * (long)BM + tid) < (long)E) {
        MBAR_ARRIVE_TX(mbar, NDIM * 2);
        BULK_CP(as_smem + (uint32_t)(tid * AS_WROW * 4),
                (const void*)(g_atom_h + s * (long)NDIM), NDIM * 2, mbar);
    } else {
        MBAR_ARRIVE(mbar);
    }
}
// fallback (n_nodes > cap): 2 threads/row
__device__ __forceinline__ void atom_fallback(uint32_t* __restrict__ As32, long tile,
                                              const float* __restrict__ atom,
                                              const void* __restrict__ src_idx,
                                              int is64, int E, long n_nodes) {
    const int tid  = threadIdx.x;
    const int r    = tid >> 1;
    const int half = tid & 1;
    const long e   = tile * (long)BM + r;
    if (e >= (long)E) return;
    long s = is64 ? (long)((const long long*)src_idx)[e]
                  : (long)((const int*)src_idx)[e];
    if (s < 0) s = 0;
    if (s >= n_nodes) s = n_nodes - 1;
    const float4* arow = (const float4*)(atom + s * (long)NDIM) + half * 16;
    uint32_t* dst = As32 + r * AS_WROW + half * 32;
    #pragma unroll
    for (int u = 0; u < 16; u++) {
        float4 v = __ldg(arow + u);
        dst[u * 2 + 0] = pack_h2(v.x, v.y);
        dst[u * 2 + 1] = pack_h2(v.z, v.w);
    }
}

__device__ __forceinline__ void load_b16(uint32_t b[16], const uint32_t* __restrict__ Wr) {
    uint4 q0 = *(const uint4*)(Wr + 0);
    uint4 q1 = *(const uint4*)(Wr + 4);
    uint4 q2 = *(const uint4*)(Wr + 8);
    uint4 q3 = *(const uint4*)(Wr + 12);
    b[0]=q0.x;  b[1]=q0.y;  b[2]=q0.z;  b[3]=q0.w;
    b[4]=q1.x;  b[5]=q1.y;  b[6]=q1.z;  b[7]=q1.w;
    b[8]=q2.x;  b[9]=q2.y;  b[10]=q2.z; b[11]=q2.w;
    b[12]=q3.x; b[13]=q3.y; b[14]=q3.z; b[15]=q3.w;
}

__global__ void __launch_bounds__(THREADS, 1)
atom2bond_kernel(const float* __restrict__ atom,
                 const float* __restrict__ edge,
                 const void*  __restrict__ src_idx,
                 const float* __restrict__ Wg,
                 const float* __restrict__ bg,
                 float* __restrict__ out,
                 int E, int ntiles, long n_nodes, int fast) {
    extern __shared__ char sm[];
    const uint32_t smb = smem_u32(sm);
    uint32_t* Wf = (uint32_t*)(sm + OFF_WF);
    float* Bs = (float*)(sm + OFF_BIAS);

    const int tid  = threadIdx.x;
    const int lane = tid & 31;
    const int warp = tid >> 5;            // 0..11
    const int g  = lane >> 2;
    const int t  = lane & 3;
    const int wm = warp >> 1;             // 0..5 : 32-edge block
    const int wn = warp & 1;              // 0..1 : 64-col half
    const int is64 = g_idx_is64;

    if (tid == 0) { MBAR_INIT(smb + OFF_MBAR, THREADS); MBAR_INIT(smb + OFF_MBAR + 8, THREADS); }
    __syncthreads();

    // ---- prologue: tile 0 into buffer 0; prefetch idx for tile 0+grid ----
    long tile = blockIdx.x;
    uint32_t* As0 = (uint32_t*)(sm + OFF_AS);
    long s_nxt;
    if (fast) {
        long s0 = idx_ld(tile, src_idx, is64, E, n_nodes);
        atom_issue(smb + OFF_AS, smb + OFF_MBAR, tile, s0, E);
    } else {
        atom_fallback(As0, tile, atom, src_idx, is64, E, n_nodes);
        MBAR_ARRIVE(smb + OFF_MBAR);
    }
    s_nxt = idx_ld(tile + gridDim.x, src_idx, is64, E, n_nodes);   // prefetch, no consumer yet
    float4 ev[8];
    edge_ldg(ev, tile, edge, E);
    edge_sts(ev, As0, tile, E);

    // ---- W fragments in smem (per-lane contiguous, stride 20 words) + bias ----
    for (int idx = tid; idx < 2 * NKK * 32 * 16; idx += THREADS) {
        const int v  = idx & 15;
        const int l  = (idx >> 4) & 31;
        const int rk = idx >> 9;
        const int kk = rk % NKK;
        const int wq = rk / NKK;
        const int j  = v >> 1;
        const int h  = v & 1;
        const int k  = kk * 16 + h * 8 + 2 * (l & 3);
        const int n  = wq * 64 + j * 8 + (l >> 2);
        Wf[((wq * NKK + kk) * 32 + l) * 20 + v] =
            pack_h2(Wg[k * NDIM + n], Wg[(k + 1) * NDIM + n]);
    }
    if (tid < NDIM) Bs[tid] = bg[tid];
    __syncthreads();

    const uint32_t* Wbase = Wf + (wn * NKK * 32 + lane) * 20;
    // per-lane ldmatrix base offset (bytes): row = wm*32 + (lane&15), chunk = lane>>4
    const uint32_t a_off = (uint32_t)((wm * 32 + (lane & 15)) * AS_WROW * 4 + (lane >> 4) * 16);

    uint32_t ph[2] = {0, 0};
    int bi = 0;
    for (;;) {
        MBAR_WAIT(smb + OFF_MBAR + bi * 8, ph[bi]);    // atoms(tile) landed in buf[bi]
        ph[bi] ^= 1;

        const long tn = tile + gridDim.x;
        const bool more = (tn < (long)ntiles);
        const int  bn = bi ^ 1;
        uint32_t* Asnxt = (uint32_t*)(sm + OFF_AS + bn * AS_BUF_BYTES);

        if (more) {
            if (fast) {
                // consume prefetched idx (no stall), then prefetch the next one
                atom_issue(smb + OFF_AS + bn * AS_BUF_BYTES, smb + OFF_MBAR + bn * 8, tn, s_nxt, E);
                s_nxt = idx_ld(tn + gridDim.x, src_idx, is64, E, n_nodes);
            }
            edge_ldg(ev, tn, edge, E);
        }

        // ---- MMA: warp = 32 edges x 64 outputs, K=192; b double-buffered ----
        float acc[2][8][4];
        #pragma unroll
        for (int i = 0; i < 2; i++)
            #pragma unroll
            for (int j = 0; j < 8; j++)
                #pragma unroll
                for (int c = 0; c < 4; c++) acc[i][j][c] = 0.f;

        const uint32_t a_base = smb + OFF_AS + (uint32_t)(bi * AS_BUF_BYTES) + a_off;

        uint32_t b[2][16];
        load_b16(b[0], Wbase);
        #pragma unroll
        for (int kk = 0; kk < NKK; kk++) {
            const int cur = kk & 1;
            if (kk < NKK - 1)
                load_b16(b[cur ^ 1], Wbase + (kk + 1) * 640);
            uint32_t a[2][4];
            ldsm_x4(a[0], a_base + kk * 32);
            ldsm_x4(a[1], a_base + 16 * AS_WROW * 4 + kk * 32);
            #pragma unroll
            for (int i = 0; i < 2; i++)
                #pragma unroll
                for (int j = 0; j < 8; j++)
                    mma_f16(acc[i][j], a[i], b[cur] + 2 * j);
        }

        // ---- epilogue(tile): bias + relu + STG from regs ----
        const long eb = tile * (long)BM;
        #pragma unroll
        for (int i = 0; i < 2; i++) {
            #pragma unroll
            for (int rr = 0; rr < 2; rr++) {
                const long e = eb + wm * 32 + i * 16 + rr * 8 + g;
                if (e < (long)E) {
                    float* orow = out + e * (long)NDIM;
                    #pragma unroll
                    for (int j = 0; j < 8; j++) {
                        const int c = wn * 64 + j * 8 + 2 * t;
                        const float2 bc = *(const float2*)(Bs + c);
                        float v0 = fmaxf(acc[i][j][rr * 2 + 0] + bc.x, 0.f);
                        float v1 = fmaxf(acc[i][j][rr * 2 + 1] + bc.y, 0.f);
                        *(float2*)(orow + c) = make_float2(v0, v1);
                    }
                }
            }
        }

        if (!more) break;

        // stage next tile's edges (and fallback atoms) into buf[bn]
        edge_sts(ev, Asnxt, tn, E);
        if (!fast) {
            atom_fallback(Asnxt, tn, atom, src_idx, is64, E, n_nodes);
            MBAR_ARRIVE(smb + OFF_MBAR + bn * 8);
        }
        __syncthreads();     // buf[bn] staging visible to all warps before next MMA

        tile = tn;
        bi = bn;
    }
}

extern "C" void kernel_launch(void* const* d_in, const int* in_sizes, int n_in,
                              void* d_out, int out_size) {
    const float* atom = (const float*)d_in[0];   // [N_NODES,128] f32
    const float* edge = (const float*)d_in[1];   // [E,64] f32
    const void*  src  = d_in[2];                 // [E] int32 or int64 (detected)
    const float* W    = (const float*)d_in[3];   // [192,128] f32
    const float* b    = (const float*)d_in[4];   // [128] f32
    float* out = (float*)d_out;                  // [E,128] f32

    const int  E       = in_sizes[2];
    const long n_atomf = (long)in_sizes[0];
    const long n_nodes = n_atomf / NDIM;
    const int  ntiles  = (E + BM - 1) / BM;
    const int  fast    = (n_nodes <= ATOM_CAP_ROWS) ? 1 : 0;

    int n_words = E < 1024 ? E : 1024;
    prep_kernel<<<148, 256>>>(atom, n_atomf, (const int*)src, n_words, fast);

    cudaFuncSetAttribute(atom2bond_kernel,
                         cudaFuncAttributeMaxDynamicSharedMemorySize, SMEM_TOTAL);

    int grid = ntiles < 148 ? ntiles : 148;
    atom2bond_kernel<<<grid, THREADS, SMEM_TOTAL>>>(atom, edge, src, W, b, out,
                                                    E, ntiles, n_nodes, fast);
}